// round 13
// baseline (speedup 1.0000x reference)
#include <cuda_runtime.h>
#include <cuda_bf16.h>

// x: (1, 256, 512, 512) fp32 -> out: (1, 64, 512, 512), mean over groups of 4 channels.
// HW4 = 512*512/4 = 65536 float4 per channel plane.
// out[c][p] = 0.25 * (x[4c][p] + x[4c+1][p] + x[4c+2][p] + x[4c+3][p])
//
// Each thread handles TWO CONSECUTIVE float4s (32B) per channel: 8 front-batched
// LDG.128 arranged as contiguous pairs -> each warp covers 8KB contiguous per
// input plane, maximizing DRAM row-buffer locality (vs 4KB in the 1-per-thread
// config). Same minimal traffic (320 MB), same occupancy.

static constexpr int HW4 = (512 * 512) / 4;   // 65536 float4 per plane
static constexpr int C_OUT = 64;
static constexpr int THREADS = 256;

__global__ __launch_bounds__(THREADS)
void spectral_blurrin_kernel(const float4* __restrict__ x,
                             float4* __restrict__ out) {
    // Each thread owns float4 indices {2t, 2t+1} within the plane.
    const int t = blockIdx.x * THREADS + threadIdx.x;
    const unsigned p = 2u * (unsigned)t;
    const int c = blockIdx.y;

    const float4* in0 = x + (long long)c * 4 * HW4 + p;

    // 8 independent LDG.128, contiguous pairs per channel (32B/thread/channel)
    const float4 a0 = in0[0];
    const float4 a1 = in0[1];
    const float4 b0 = in0[HW4];
    const float4 b1 = in0[HW4 + 1];
    const float4 d0 = in0[2 * HW4];
    const float4 d1 = in0[2 * HW4 + 1];
    const float4 e0 = in0[3 * HW4];
    const float4 e1 = in0[3 * HW4 + 1];

    float4 r0, r1;
    r0.x = (a0.x + b0.x + d0.x + e0.x) * 0.25f;
    r0.y = (a0.y + b0.y + d0.y + e0.y) * 0.25f;
    r0.z = (a0.z + b0.z + d0.z + e0.z) * 0.25f;
    r0.w = (a0.w + b0.w + d0.w + e0.w) * 0.25f;
    r1.x = (a1.x + b1.x + d1.x + e1.x) * 0.25f;
    r1.y = (a1.y + b1.y + d1.y + e1.y) * 0.25f;
    r1.z = (a1.z + b1.z + d1.z + e1.z) * 0.25f;
    r1.w = (a1.w + b1.w + d1.w + e1.w) * 0.25f;

    float4* o = out + (long long)c * HW4 + p;
    o[0] = r0;
    o[1] = r1;
}

extern "C" void kernel_launch(void* const* d_in, const int* in_sizes, int n_in,
                              void* d_out, int out_size) {
    const float4* x = (const float4*)d_in[0];
    float4* out = (float4*)d_out;

    dim3 grid(HW4 / (2 * THREADS), C_OUT);   // (128, 64) = 8192 blocks
    spectral_blurrin_kernel<<<grid, THREADS>>>(x, out);
}

// round 15
// speedup vs baseline: 1.0458x; 1.0458x over previous
#include <cuda_runtime.h>
#include <cuda_bf16.h>

// x: (1, 256, 512, 512) fp32 -> out: (1, 64, 512, 512), mean over groups of 4 channels.
// HW4 = 512*512/4 = 65536 float4 per channel plane.
// out[c][p] = 0.25 * (x[4c][p] + x[4c+1][p] + x[4c+2][p] + x[4c+3][p])
//
// FINAL converged config (best measured kernel time, 46.4-46.5us across runs):
//  - one output float4 per thread, lanes fully coalesced (128B per warp request)
//  - 4 independent front-batched LDG.128 per thread (MLP=4), planes 1MB apart
//  - __ldcs/__stcs: single-touch data, evict-first keeps L2 sectors for
//    in-flight traffic (measured ~2.3% faster kernel vs default policy)
//  - 512-thread blocks, 8192-block wave launch (max occupancy)
// Runs at ~6.65 TB/s; traffic is minimal (320 MB). Alternatives measured and
// rejected: MLP=8 split-halves (spread), persistent grid (occupancy loss),
// 2-consecutive-float4/thread (breaks within-instruction coalescing).

static constexpr int HW4 = (512 * 512) / 4;   // 65536
static constexpr int C_OUT = 64;
static constexpr int THREADS = 512;

__global__ __launch_bounds__(THREADS)
void spectral_blurrin_kernel(const float4* __restrict__ x,
                             float4* __restrict__ out) {
    const int p = blockIdx.x * THREADS + threadIdx.x;   // position within plane (float4 units)
    const int c = blockIdx.y;                           // output channel

    const float4* in0 = x + (long long)c * 4 * HW4 + p;

    // 4 independent 128-bit streaming loads, 1 MB apart -> front-batched, MLP=4
    const float4 a = __ldcs(in0);
    const float4 b = __ldcs(in0 + HW4);
    const float4 d = __ldcs(in0 + 2 * HW4);
    const float4 e = __ldcs(in0 + 3 * HW4);

    float4 r;
    r.x = (a.x + b.x + d.x + e.x) * 0.25f;
    r.y = (a.y + b.y + d.y + e.y) * 0.25f;
    r.z = (a.z + b.z + d.z + e.z) * 0.25f;
    r.w = (a.w + b.w + d.w + e.w) * 0.25f;

    __stcs(out + (long long)c * HW4 + p, r);
}

extern "C" void kernel_launch(void* const* d_in, const int* in_sizes, int n_in,
                              void* d_out, int out_size) {
    const float4* x = (const float4*)d_in[0];
    float4* out = (float4*)d_out;

    dim3 grid(HW4 / THREADS, C_OUT);   // (128, 64) = 8192 blocks
    spectral_blurrin_kernel<<<grid, THREADS>>>(x, out);
}

// round 16
// speedup vs baseline: 1.0504x; 1.0044x over previous
#include <cuda_runtime.h>
#include <cuda_bf16.h>

// x: (1, 256, 512, 512) fp32 -> out: (1, 64, 512, 512), mean over groups of 4 channels.
// HW4 = 512*512/4 = 65536 float4 per channel plane.
// out[c][p] = 0.25 * (x[4c][p] + x[4c+1][p] + x[4c+2][p] + x[4c+3][p])
//
// CONVERGED OPTIMUM (fastest measured kernel time: 45.79us, DRAM=84.5%,
// 6.69 TB/s). Session-measured design space:
//  - one output float4 per thread, lanes fully coalesced (128B/warp request)
//  - 4 independent front-batched LDG.128 (MLP=4), input planes 1MB apart
//  - __ldcs/__stcs: single-touch stream, evict-first (measured ~2-4% faster
//    kernel vs default cache policy across two runs)
//  - 512-thread blocks, 8192-block wave launch
// Rejected by measurement: MLP=8 split-halves, persistent 592-CTA grid
// (occupancy -> DRAM 77.9%), 2-consecutive-float4/thread (sector-split,
// DRAM 81.2%), plain cache policy (47.5us). Traffic is minimal (320MB);
// remaining gap to 8TB/s spec is HBM controller turnaround, not addressable.

static constexpr int HW4 = (512 * 512) / 4;   // 65536
static constexpr int C_OUT = 64;
static constexpr int THREADS = 512;

__global__ __launch_bounds__(THREADS)
void spectral_blurrin_kernel(const float4* __restrict__ x,
                             float4* __restrict__ out) {
    const int p = blockIdx.x * THREADS + threadIdx.x;   // position within plane (float4 units)
    const int c = blockIdx.y;                           // output channel

    const float4* in0 = x + (long long)c * 4 * HW4 + p;

    // 4 independent 128-bit streaming loads, 1 MB apart -> front-batched, MLP=4
    const float4 a = __ldcs(in0);
    const float4 b = __ldcs(in0 + HW4);
    const float4 d = __ldcs(in0 + 2 * HW4);
    const float4 e = __ldcs(in0 + 3 * HW4);

    float4 r;
    r.x = (a.x + b.x + d.x + e.x) * 0.25f;
    r.y = (a.y + b.y + d.y + e.y) * 0.25f;
    r.z = (a.z + b.z + d.z + e.z) * 0.25f;
    r.w = (a.w + b.w + d.w + e.w) * 0.25f;

    __stcs(out + (long long)c * HW4 + p, r);
}

extern "C" void kernel_launch(void* const* d_in, const int* in_sizes, int n_in,
                              void* d_out, int out_size) {
    const float4* x = (const float4*)d_in[0];
    float4* out = (float4*)d_out;

    dim3 grid(HW4 / THREADS, C_OUT);   // (128, 64) = 8192 blocks
    spectral_blurrin_kernel<<<grid, THREADS>>>(x, out);
}